// round 1
// baseline (speedup 1.0000x reference)
#include <cuda_runtime.h>

#define Nn 50000
#define Ee 800000
#define ET (Ee + Nn)
#define F 128

// ---- scratch (device globals; no allocations) ----
__device__ float    g_h  [Nn * F];   // post-GEMM features, current layer
__device__ float    g_agg[Nn * F];   // scatter accumulator
__device__ float    g_buf[Nn * F];   // layer output -> next layer input
__device__ float    g_al_s[Nn * 8];  // per-node, per-head src logits
__device__ float    g_al_d[Nn * 8];  // per-node, per-head dst logits
__device__ unsigned g_m  [Nn * 8];   // encoded segment max
__device__ float    g_s  [Nn * 8];   // segment sum of exp

// order-preserving float <-> uint for atomicMax (handles negatives)
__device__ __forceinline__ unsigned fenc(float f) {
    unsigned u = __float_as_uint(f);
    return (u & 0x80000000u) ? ~u : (u | 0x80000000u);
}
__device__ __forceinline__ float fdec(unsigned u) {
    return __uint_as_float((u & 0x80000000u) ? (u & 0x7FFFFFFFu) : ~u);
}
__device__ __forceinline__ float lrelu(float v) { return v > 0.f ? v : 0.2f * v; }

// GEMM h = x@W for 4 nodes/block + per-head attention logits + zero accumulators.
__global__ void gemm_attn(const float* __restrict__ xg, int use_buf,
                          const float* __restrict__ W,
                          const float* __restrict__ asv,
                          const float* __restrict__ adv, int H)
{
    const float* xin = use_buf ? g_buf : xg;
    __shared__ float xs[4][F];
    __shared__ float rs[F], rd[F];
    int j  = threadIdx.x;
    int n0 = blockIdx.x * 4;
#pragma unroll
    for (int i = 0; i < 4; i++) xs[i][j] = xin[(n0 + i) * F + j];
    __syncthreads();

    float acc0 = 0.f, acc1 = 0.f, acc2 = 0.f, acc3 = 0.f;
#pragma unroll 8
    for (int k = 0; k < F; k++) {
        float w = W[k * F + j];
        acc0 += xs[0][k] * w;
        acc1 += xs[1][k] * w;
        acc2 += xs[2][k] * w;
        acc3 += xs[3][k] * w;
    }
    float av = asv[j], dv = adv[j];
    int   C  = F / H;
#pragma unroll
    for (int i = 0; i < 4; i++) {
        float acc = (i == 0) ? acc0 : (i == 1) ? acc1 : (i == 2) ? acc2 : acc3;
        int   n   = n0 + i;
        g_h[n * F + j]   = acc;
        g_agg[n * F + j] = 0.f;
        rs[j] = acc * av;
        rd[j] = acc * dv;
        __syncthreads();
        if (j < H) {
            float ss = 0.f, dd = 0.f;
            for (int c = 0; c < C; c++) { ss += rs[j * C + c]; dd += rd[j * C + c]; }
            g_al_s[n * 8 + j] = ss;
            g_al_d[n * 8 + j] = dd;
            g_m[n * 8 + j]    = 0u;     // below fenc() of any finite float
            g_s[n * 8 + j]    = 0.f;
        }
        __syncthreads();
    }
}

__global__ void edge_max(const int* __restrict__ ei, int H)
{
    int t = blockIdx.x * blockDim.x + threadIdx.x;
    if (t >= ET * H) return;
    int e = t / H, hd = t - e * H;
    int src, dst;
    if (e < Ee) { src = ei[e]; dst = ei[Ee + e]; }
    else        { src = dst = e - Ee; }
    float v = lrelu(g_al_s[src * 8 + hd] + g_al_d[dst * 8 + hd]);
    atomicMax(&g_m[dst * 8 + hd], fenc(v));
}

__global__ void edge_sum(const int* __restrict__ ei, int H)
{
    int t = blockIdx.x * blockDim.x + threadIdx.x;
    if (t >= ET * H) return;
    int e = t / H, hd = t - e * H;
    int src, dst;
    if (e < Ee) { src = ei[e]; dst = ei[Ee + e]; }
    else        { src = dst = e - Ee; }
    float v  = lrelu(g_al_s[src * 8 + hd] + g_al_d[dst * 8 + hd]);
    float ex = expf(v - fdec(g_m[dst * 8 + hd]));
    atomicAdd(&g_s[dst * 8 + hd], ex);
}

// one block per edge; 128 threads cover all features
__global__ void edge_scatter(const int* __restrict__ ei, int H)
{
    int e = blockIdx.x;
    int f = threadIdx.x;
    int src, dst;
    if (e < Ee) { src = ei[e]; dst = ei[Ee + e]; }
    else        { src = dst = e - Ee; }
    int   hd    = (f * H) >> 7;     // f / (128/H)
    float v     = lrelu(g_al_s[src * 8 + hd] + g_al_d[dst * 8 + hd]);
    float alpha = expf(v - fdec(g_m[dst * 8 + hd])) / g_s[dst * 8 + hd];
    atomicAdd(&g_agg[dst * F + f], g_h[src * F + f] * alpha);
}

__global__ void ln_act(const float* __restrict__ b, const float* __restrict__ gg,
                       const float* __restrict__ be, float* out, int do_elu)
{
    int n = blockIdx.x, j = threadIdx.x;
    float v = g_agg[n * F + j] + b[j];

    __shared__ float sh[4];
    float s1 = v;
#pragma unroll
    for (int o = 16; o > 0; o >>= 1) s1 += __shfl_xor_sync(0xffffffffu, s1, o);
    if ((j & 31) == 0) sh[j >> 5] = s1;
    __syncthreads();
    float mu = (sh[0] + sh[1] + sh[2] + sh[3]) * (1.f / F);
    float d  = v - mu;
    __syncthreads();
    float s2 = d * d;
#pragma unroll
    for (int o = 16; o > 0; o >>= 1) s2 += __shfl_xor_sync(0xffffffffu, s2, o);
    if ((j & 31) == 0) sh[j >> 5] = s2;
    __syncthreads();
    float var = (sh[0] + sh[1] + sh[2] + sh[3]) * (1.f / F);

    float y = d * rsqrtf(var + 1e-5f) * gg[j] + be[j];
    if (do_elu && y < 0.f) y = expf(y) - 1.f;
    float* o = out ? out : g_buf;
    o[n * F + j] = y;
}

extern "C" void kernel_launch(void* const* d_in, const int* in_sizes, int n_in,
                              void* d_out, int out_size)
{
    const float* x  = (const float*)d_in[0];
    const int*   ei = (const int*)d_in[1];

    for (int l = 0; l < 3; l++) {
        const float* W   = (const float*)d_in[2 + 6 * l];
        const float* as_ = (const float*)d_in[3 + 6 * l];
        const float* ad_ = (const float*)d_in[4 + 6 * l];
        const float* b   = (const float*)d_in[5 + 6 * l];
        const float* g   = (const float*)d_in[6 + 6 * l];
        const float* be  = (const float*)d_in[7 + 6 * l];
        int H = (l == 2) ? 1 : 8;

        gemm_attn<<<Nn / 4, 128>>>(x, l > 0 ? 1 : 0, W, as_, ad_, H);

        int nth = ET * H;
        edge_max<<<(nth + 255) / 256, 256>>>(ei, H);
        edge_sum<<<(nth + 255) / 256, 256>>>(ei, H);
        edge_scatter<<<ET, 128>>>(ei, H);

        ln_act<<<Nn, 128>>>(b, g, be, (l == 2) ? (float*)d_out : nullptr,
                            (l < 2) ? 1 : 0);
    }
}

// round 2
// speedup vs baseline: 2.2479x; 2.2479x over previous
#include <cuda_runtime.h>

#define Nn 50000
#define Ee 800000
#define ET (Ee + Nn)
#define F 128

// ---- scratch (device globals; no allocations) ----
__device__ float    g_h  [Nn * F];   // post-GEMM features, current layer
__device__ float    g_agg[Nn * F];   // scatter accumulator (unnormalized)
__device__ float    g_buf[Nn * F];   // layer output -> next layer input
__device__ float    g_al_s[Nn * 8];  // per-node, per-head src logits
__device__ float    g_al_d[Nn * 8];  // per-node, per-head dst logits
__device__ unsigned g_m  [Nn * 8];   // encoded segment max
__device__ float    g_s  [Nn * 8];   // segment sum of exp

// order-preserving float <-> uint for atomicMax (handles negatives)
__device__ __forceinline__ unsigned fenc(float f) {
    unsigned u = __float_as_uint(f);
    return (u & 0x80000000u) ? ~u : (u | 0x80000000u);
}
__device__ __forceinline__ float fdec(unsigned u) {
    return __uint_as_float((u & 0x80000000u) ? (u & 0x7FFFFFFFu) : ~u);
}
__device__ __forceinline__ float lrelu(float v) { return v > 0.f ? v : 0.2f * v; }

// GEMM h = x@W for 4 nodes/block + per-head attention logits + zero accumulators.
__global__ void gemm_attn(const float* __restrict__ xg, int use_buf,
                          const float* __restrict__ W,
                          const float* __restrict__ asv,
                          const float* __restrict__ adv, int H)
{
    const float* xin = use_buf ? g_buf : xg;
    __shared__ float xs[4][F];
    __shared__ float rs[F], rd[F];
    int j  = threadIdx.x;
    int n0 = blockIdx.x * 4;
#pragma unroll
    for (int i = 0; i < 4; i++) xs[i][j] = xin[(n0 + i) * F + j];
    __syncthreads();

    float acc0 = 0.f, acc1 = 0.f, acc2 = 0.f, acc3 = 0.f;
#pragma unroll 8
    for (int k = 0; k < F; k++) {
        float w = W[k * F + j];
        acc0 += xs[0][k] * w;
        acc1 += xs[1][k] * w;
        acc2 += xs[2][k] * w;
        acc3 += xs[3][k] * w;
    }
    float av = asv[j], dv = adv[j];
    int   C  = F / H;
#pragma unroll
    for (int i = 0; i < 4; i++) {
        float acc = (i == 0) ? acc0 : (i == 1) ? acc1 : (i == 2) ? acc2 : acc3;
        int   n   = n0 + i;
        g_h[n * F + j]   = acc;
        g_agg[n * F + j] = 0.f;
        rs[j] = acc * av;
        rd[j] = acc * dv;
        __syncthreads();
        if (j < H) {
            float ss = 0.f, dd = 0.f;
            for (int c = 0; c < C; c++) { ss += rs[j * C + c]; dd += rd[j * C + c]; }
            g_al_s[n * 8 + j] = ss;
            g_al_d[n * 8 + j] = dd;
            g_m[n * 8 + j]    = 0u;     // below fenc() of any finite float
            g_s[n * 8 + j]    = 0.f;
        }
        __syncthreads();
    }
}

// one thread per edge, all heads; vectorized logit loads
__global__ void edge_max(const int* __restrict__ ei, int H)
{
    int e = blockIdx.x * blockDim.x + threadIdx.x;
    if (e >= ET) return;
    int src, dst;
    if (e < Ee) { src = ei[e]; dst = ei[Ee + e]; }
    else        { src = dst = e - Ee; }
    if (H == 8) {
        float4 s0 = *reinterpret_cast<const float4*>(&g_al_s[src * 8]);
        float4 s1 = *reinterpret_cast<const float4*>(&g_al_s[src * 8 + 4]);
        float4 d0 = *reinterpret_cast<const float4*>(&g_al_d[dst * 8]);
        float4 d1 = *reinterpret_cast<const float4*>(&g_al_d[dst * 8 + 4]);
        unsigned* mp = &g_m[dst * 8];
        atomicMax(mp + 0, fenc(lrelu(s0.x + d0.x)));
        atomicMax(mp + 1, fenc(lrelu(s0.y + d0.y)));
        atomicMax(mp + 2, fenc(lrelu(s0.z + d0.z)));
        atomicMax(mp + 3, fenc(lrelu(s0.w + d0.w)));
        atomicMax(mp + 4, fenc(lrelu(s1.x + d1.x)));
        atomicMax(mp + 5, fenc(lrelu(s1.y + d1.y)));
        atomicMax(mp + 6, fenc(lrelu(s1.z + d1.z)));
        atomicMax(mp + 7, fenc(lrelu(s1.w + d1.w)));
    } else {
        float v = lrelu(g_al_s[src * 8] + g_al_d[dst * 8]);
        atomicMax(&g_m[dst * 8], fenc(v));
    }
}

// one WARP per edge: lanes 0-7 compute exp(e-m) per head (+ sum atomics),
// every lane accumulates 4 features via a single v4 vector reduction.
__global__ void edge_scatter(const int* __restrict__ ei, int H)
{
    int w = (blockIdx.x * blockDim.x + threadIdx.x) >> 5;
    if (w >= ET) return;
    int lane = threadIdx.x & 31;
    int src, dst;
    if (w < Ee) { src = ei[w]; dst = ei[Ee + w]; }
    else        { src = dst = w - Ee; }

    float ex = 0.f;
    if (H == 8) {
        if (lane < 8) {
            float v = lrelu(g_al_s[src * 8 + lane] + g_al_d[dst * 8 + lane]);
            ex = expf(v - fdec(g_m[dst * 8 + lane]));
            atomicAdd(&g_s[dst * 8 + lane], ex);
        }
        ex = __shfl_sync(0xffffffffu, ex, lane >> 2);  // head = (lane*4)/16
    } else {
        if (lane == 0) {
            float v = lrelu(g_al_s[src * 8] + g_al_d[dst * 8]);
            ex = expf(v - fdec(g_m[dst * 8]));
            atomicAdd(&g_s[dst * 8], ex);
        }
        ex = __shfl_sync(0xffffffffu, ex, 0);
    }

    float4 hv = *reinterpret_cast<const float4*>(&g_h[src * F + lane * 4]);
    float4 r  = make_float4(hv.x * ex, hv.y * ex, hv.z * ex, hv.w * ex);
    asm volatile("red.global.add.v4.f32 [%0], {%1,%2,%3,%4};"
                 :: "l"(&g_agg[dst * F + lane * 4]),
                    "f"(r.x), "f"(r.y), "f"(r.z), "f"(r.w)
                 : "memory");
}

__global__ void ln_act(const float* __restrict__ b, const float* __restrict__ gg,
                       const float* __restrict__ be, float* out, int do_elu, int H)
{
    int n = blockIdx.x, j = threadIdx.x;
    int hd = (j * H) >> 7;
    float v = g_agg[n * F + j] / g_s[n * 8 + hd] + b[j];

    __shared__ float sh[4];
    float s1 = v;
#pragma unroll
    for (int o = 16; o > 0; o >>= 1) s1 += __shfl_xor_sync(0xffffffffu, s1, o);
    if ((j & 31) == 0) sh[j >> 5] = s1;
    __syncthreads();
    float mu = (sh[0] + sh[1] + sh[2] + sh[3]) * (1.f / F);
    float d  = v - mu;
    __syncthreads();
    float s2 = d * d;
#pragma unroll
    for (int o = 16; o > 0; o >>= 1) s2 += __shfl_xor_sync(0xffffffffu, s2, o);
    if ((j & 31) == 0) sh[j >> 5] = s2;
    __syncthreads();
    float var = (sh[0] + sh[1] + sh[2] + sh[3]) * (1.f / F);

    float y = d * rsqrtf(var + 1e-5f) * gg[j] + be[j];
    if (do_elu && y < 0.f) y = expf(y) - 1.f;
    float* o = out ? out : g_buf;
    o[n * F + j] = y;
}

extern "C" void kernel_launch(void* const* d_in, const int* in_sizes, int n_in,
                              void* d_out, int out_size)
{
    const float* x  = (const float*)d_in[0];
    const int*   ei = (const int*)d_in[1];

    for (int l = 0; l < 3; l++) {
        const float* W   = (const float*)d_in[2 + 6 * l];
        const float* as_ = (const float*)d_in[3 + 6 * l];
        const float* ad_ = (const float*)d_in[4 + 6 * l];
        const float* b   = (const float*)d_in[5 + 6 * l];
        const float* g   = (const float*)d_in[6 + 6 * l];
        const float* be  = (const float*)d_in[7 + 6 * l];
        int H = (l == 2) ? 1 : 8;

        gemm_attn<<<Nn / 4, 128>>>(x, l > 0 ? 1 : 0, W, as_, ad_, H);

        edge_max<<<(ET + 255) / 256, 256>>>(ei, H);

        // one warp per edge: 8 edges per 256-thread block
        edge_scatter<<<(ET + 7) / 8, 256>>>(ei, H);

        ln_act<<<Nn, 128>>>(b, g, be, (l == 2) ? (float*)d_out : nullptr,
                            (l < 2) ? 1 : 0, H);
    }
}

// round 3
// speedup vs baseline: 4.0827x; 1.8163x over previous
#include <cuda_runtime.h>

#define Nn 50000
#define Ee 800000
#define ET (Ee + Nn)
#define F 128
#define NB 16          // nodes per gemm block

// ---- scratch (device globals; no allocations) ----
__device__ float g_h   [Nn * F];
__device__ float g_buf [Nn * F];
__device__ float g_al_s[Nn * 8];
__device__ float g_al_d[Nn * 8];
__device__ int   g_cnt [Nn];
__device__ int   g_rp  [Nn + 1];
__device__ int   g_cur [Nn];
__device__ int   g_col [ET];       // src node per incoming edge, grouped by dst

__device__ __forceinline__ float lrelu(float v) { return v > 0.f ? v : 0.2f * v; }

// ================= CSR build (once per launch) =================
__global__ void csr_zero()
{
    int i = blockIdx.x * blockDim.x + threadIdx.x;
    if (i < Nn) g_cnt[i] = 0;
}

__global__ void csr_hist(const int* __restrict__ ei)
{
    int e = blockIdx.x * blockDim.x + threadIdx.x;
    if (e >= ET) return;
    int dst = (e < Ee) ? ei[Ee + e] : e - Ee;
    atomicAdd(&g_cnt[dst], 1);
}

__global__ void csr_scan()   // single block, 1024 threads
{
    __shared__ int sp[1024];
    int t = threadIdx.x;
    const int CH = (Nn + 1023) / 1024;
    int base = t * CH;
    int s = 0;
    for (int i = 0; i < CH; i++) { int idx = base + i; if (idx < Nn) s += g_cnt[idx]; }
    sp[t] = s;
    __syncthreads();
    for (int off = 1; off < 1024; off <<= 1) {
        int v = (t >= off) ? sp[t - off] : 0;
        __syncthreads();
        sp[t] += v;
        __syncthreads();
    }
    int run = (t == 0) ? 0 : sp[t - 1];
    for (int i = 0; i < CH; i++) {
        int idx = base + i;
        if (idx < Nn) { g_rp[idx] = run; g_cur[idx] = run; run += g_cnt[idx]; }
    }
    if (t == 1023) g_rp[Nn] = ET;
}

__global__ void csr_fill(const int* __restrict__ ei)
{
    int e = blockIdx.x * blockDim.x + threadIdx.x;
    if (e >= ET) return;
    int src, dst;
    if (e < Ee) { src = ei[e]; dst = ei[Ee + e]; }
    else        { src = dst = e - Ee; }
    int pos = atomicAdd(&g_cur[dst], 1);
    g_col[pos] = src;
}

// ================= GEMM + attention logits =================
// block = 128 threads = 4 warps; warp ng owns nodes n0+4ng..+3, lane cg owns cols 4cg..4cg+3.
__global__ void gemm_attn(const float* __restrict__ xg, int use_buf,
                          const float* __restrict__ W,
                          const float* __restrict__ asv,
                          const float* __restrict__ adv, int H)
{
    const float* xin = use_buf ? g_buf : xg;
    __shared__ __align__(16) float xs[F][20];   // [k][node_local], padded

    int tid = threadIdx.x;
    int cg  = tid & 31;
    int ng  = tid >> 5;
    int n0  = blockIdx.x * NB;

#pragma unroll
    for (int i = 0; i < NB; i++) xs[tid][i] = xin[(n0 + i) * F + tid];
    __syncthreads();

    float4 acc[4];
#pragma unroll
    for (int a = 0; a < 4; a++) acc[a] = make_float4(0.f, 0.f, 0.f, 0.f);

#pragma unroll 4
    for (int k = 0; k < F; k++) {
        float4 xv = *reinterpret_cast<const float4*>(&xs[k][ng * 4]);   // broadcast
        float4 wv = *reinterpret_cast<const float4*>(&W[k * F + cg * 4]);
        acc[0].x += xv.x * wv.x; acc[0].y += xv.x * wv.y; acc[0].z += xv.x * wv.z; acc[0].w += xv.x * wv.w;
        acc[1].x += xv.y * wv.x; acc[1].y += xv.y * wv.y; acc[1].z += xv.y * wv.z; acc[1].w += xv.y * wv.w;
        acc[2].x += xv.z * wv.x; acc[2].y += xv.z * wv.y; acc[2].z += xv.z * wv.z; acc[2].w += xv.z * wv.w;
        acc[3].x += xv.w * wv.x; acc[3].y += xv.w * wv.y; acc[3].z += xv.w * wv.z; acc[3].w += xv.w * wv.w;
    }

    float4 av = *reinterpret_cast<const float4*>(&asv[cg * 4]);
    float4 dv = *reinterpret_cast<const float4*>(&adv[cg * 4]);

#pragma unroll
    for (int a = 0; a < 4; a++) {
        int n = n0 + ng * 4 + a;
        *reinterpret_cast<float4*>(&g_h[n * F + cg * 4]) = acc[a];
        float ps = acc[a].x * av.x + acc[a].y * av.y + acc[a].z * av.z + acc[a].w * av.w;
        float pd = acc[a].x * dv.x + acc[a].y * dv.y + acc[a].z * dv.z + acc[a].w * dv.w;
        if (H == 8) {
            ps += __shfl_xor_sync(0xffffffffu, ps, 1);
            ps += __shfl_xor_sync(0xffffffffu, ps, 2);
            pd += __shfl_xor_sync(0xffffffffu, pd, 1);
            pd += __shfl_xor_sync(0xffffffffu, pd, 2);
            if ((cg & 3) == 0) {
                g_al_s[n * 8 + (cg >> 2)] = ps;
                g_al_d[n * 8 + (cg >> 2)] = pd;
            }
        } else {
#pragma unroll
            for (int o = 1; o < 32; o <<= 1) {
                ps += __shfl_xor_sync(0xffffffffu, ps, o);
                pd += __shfl_xor_sync(0xffffffffu, pd, o);
            }
            if (cg == 0) { g_al_s[n * 8] = ps; g_al_d[n * 8] = pd; }
        }
    }
}

// ================= fused per-node softmax-aggregate + LN (+ELU) =================
// one warp per dst node; lane owns features lane*4..lane*4+3 (head = lane>>2)
__global__ void node_agg(const float* __restrict__ b, const float* __restrict__ gg,
                         const float* __restrict__ be, float* __restrict__ out,
                         int do_elu, int H)
{
    int n = blockIdx.x * 8 + (threadIdx.x >> 5);
    if (n >= Nn) return;
    int lane = threadIdx.x & 31;

    int begin = g_rp[n], end = g_rp[n + 1];
    float4 acc = make_float4(0.f, 0.f, 0.f, 0.f);
    float  ssum = 0.f;

    if (H == 8) {
        float ald = g_al_d[n * 8 + (lane & 7)];
        int i = begin;
        for (; i + 2 <= end; i += 2) {
            int s0 = g_col[i], s1 = g_col[i + 1];
            float ex0 = 0.f, ex1 = 0.f;
            if (lane < 8) {
                ex0 = __expf(lrelu(g_al_s[s0 * 8 + lane] + ald));
                ex1 = __expf(lrelu(g_al_s[s1 * 8 + lane] + ald));
                ssum += ex0 + ex1;
            }
            float e0 = __shfl_sync(0xffffffffu, ex0, lane >> 2);
            float e1 = __shfl_sync(0xffffffffu, ex1, lane >> 2);
            float4 h0 = *reinterpret_cast<const float4*>(&g_h[s0 * F + lane * 4]);
            float4 h1 = *reinterpret_cast<const float4*>(&g_h[s1 * F + lane * 4]);
            acc.x += h0.x * e0 + h1.x * e1;
            acc.y += h0.y * e0 + h1.y * e1;
            acc.z += h0.z * e0 + h1.z * e1;
            acc.w += h0.w * e0 + h1.w * e1;
        }
        if (i < end) {
            int s0 = g_col[i];
            float ex0 = 0.f;
            if (lane < 8) {
                ex0 = __expf(lrelu(g_al_s[s0 * 8 + lane] + ald));
                ssum += ex0;
            }
            float e0 = __shfl_sync(0xffffffffu, ex0, lane >> 2);
            float4 h0 = *reinterpret_cast<const float4*>(&g_h[s0 * F + lane * 4]);
            acc.x += h0.x * e0; acc.y += h0.y * e0; acc.z += h0.z * e0; acc.w += h0.w * e0;
        }
        ssum = __shfl_sync(0xffffffffu, ssum, lane >> 2);   // per-head sum
    } else {
        float ald = g_al_d[n * 8];
        for (int i = begin; i < end; i++) {
            int s0 = g_col[i];
            float ex0 = __expf(lrelu(g_al_s[s0 * 8] + ald));   // same in all lanes
            ssum += ex0;
            float4 h0 = *reinterpret_cast<const float4*>(&g_h[s0 * F + lane * 4]);
            acc.x += h0.x * ex0; acc.y += h0.y * ex0; acc.z += h0.z * ex0; acc.w += h0.w * ex0;
        }
    }

    float inv = 1.f / ssum;
    float4 bv = *reinterpret_cast<const float4*>(&b[lane * 4]);
    acc.x = acc.x * inv + bv.x;
    acc.y = acc.y * inv + bv.y;
    acc.z = acc.z * inv + bv.z;
    acc.w = acc.w * inv + bv.w;

    // LayerNorm across the 128 features held by this warp
    float t = acc.x + acc.y + acc.z + acc.w;
#pragma unroll
    for (int o = 1; o < 32; o <<= 1) t += __shfl_xor_sync(0xffffffffu, t, o);
    float mu = t * (1.f / F);
    float dx = acc.x - mu, dy = acc.y - mu, dz = acc.z - mu, dw = acc.w - mu;
    float v = dx * dx + dy * dy + dz * dz + dw * dw;
#pragma unroll
    for (int o = 1; o < 32; o <<= 1) v += __shfl_xor_sync(0xffffffffu, v, o);
    float rstd = rsqrtf(v * (1.f / F) + 1e-5f);

    float4 gv  = *reinterpret_cast<const float4*>(&gg[lane * 4]);
    float4 bev = *reinterpret_cast<const float4*>(&be[lane * 4]);
    float4 y;
    y.x = dx * rstd * gv.x + bev.x;
    y.y = dy * rstd * gv.y + bev.y;
    y.z = dz * rstd * gv.z + bev.z;
    y.w = dw * rstd * gv.w + bev.w;
    if (do_elu) {
        if (y.x < 0.f) y.x = __expf(y.x) - 1.f;
        if (y.y < 0.f) y.y = __expf(y.y) - 1.f;
        if (y.z < 0.f) y.z = __expf(y.z) - 1.f;
        if (y.w < 0.f) y.w = __expf(y.w) - 1.f;
    }
    float* o = out ? out : g_buf;
    *reinterpret_cast<float4*>(&o[n * F + lane * 4]) = y;
}

extern "C" void kernel_launch(void* const* d_in, const int* in_sizes, int n_in,
                              void* d_out, int out_size)
{
    const float* x  = (const float*)d_in[0];
    const int*   ei = (const int*)d_in[1];

    csr_zero<<<(Nn + 255) / 256, 256>>>();
    csr_hist<<<(ET + 255) / 256, 256>>>(ei);
    csr_scan<<<1, 1024>>>();
    csr_fill<<<(ET + 255) / 256, 256>>>(ei);

    for (int l = 0; l < 3; l++) {
        const float* W   = (const float*)d_in[2 + 6 * l];
        const float* as_ = (const float*)d_in[3 + 6 * l];
        const float* ad_ = (const float*)d_in[4 + 6 * l];
        const float* b   = (const float*)d_in[5 + 6 * l];
        const float* g   = (const float*)d_in[6 + 6 * l];
        const float* be  = (const float*)d_in[7 + 6 * l];
        int H = (l == 2) ? 1 : 8;

        gemm_attn<<<Nn / NB + (Nn % NB ? 1 : 0), 128>>>(x, l > 0 ? 1 : 0, W, as_, ad_, H);
        node_agg<<<(Nn + 7) / 8, 256>>>(b, g, be, (l == 2) ? (float*)d_out : nullptr,
                                        (l < 2) ? 1 : 0, H);
    }
}